// round 3
// baseline (speedup 1.0000x reference)
#include <cuda_runtime.h>
#include <stdint.h>

#define NN      100000
#define EE      3200000
#define INDIM   512
#define HIDD    256
#define NCLS    16

// ---------------- static device scratch ------------------------------------
__device__ float g_A1[(size_t)NN * INDIM];
__device__ float g_t1[(size_t)NN * HIDD];
__device__ float g_h [(size_t)NN * HIDD];
__device__ float g_A2[(size_t)NN * HIDD];
__device__ float g_A3[(size_t)NN * HIDD];
__device__ float g_mulv_pre[NN * 32];
__device__ float g_mulv    [NN * 32];
__device__ int   g_outdeg[NN];
__device__ int   g_indeg [NN];
__device__ int   g_fill  [NN];
__device__ int   g_off   [NN + 1];
__device__ int   g_csr   [EE];
__device__ float g_out_is[NN];
__device__ float g_in_is [NN];
__device__ float g_part  [512 * 512];
__device__ float g_stats [512];

// ---------------- threefry2x32 (JAX-exact core) -----------------------------
__host__ __device__ __forceinline__ void tf2x32(uint32_t k0, uint32_t k1,
                                                uint32_t x0, uint32_t x1,
                                                uint32_t &o0, uint32_t &o1)
{
    uint32_t ks2 = k0 ^ k1 ^ 0x1BD11BDAu;
#define TF_ROT(v, r) (((v) << (r)) | ((v) >> (32 - (r))))
#define TF_RND(r) { x0 += x1; x1 = TF_ROT(x1, r); x1 ^= x0; }
    x0 += k0; x1 += k1;
    TF_RND(13) TF_RND(15) TF_RND(26) TF_RND(6)
    x0 += k1;  x1 += ks2 + 1u;
    TF_RND(17) TF_RND(29) TF_RND(16) TF_RND(24)
    x0 += ks2; x1 += k0 + 2u;
    TF_RND(13) TF_RND(15) TF_RND(26) TF_RND(6)
    x0 += k0;  x1 += k1 + 3u;
    TF_RND(17) TF_RND(29) TF_RND(16) TF_RND(24)
    x0 += k1;  x1 += ks2 + 4u;
    TF_RND(13) TF_RND(15) TF_RND(26) TF_RND(6)
    x0 += ks2; x1 += k0 + 5u;
    o0 = x0; o1 = x1;
#undef TF_RND
#undef TF_ROT
}

// partitionable random_bits(32): counter (hi=0, lo=j), bits = o0 ^ o1
__device__ __forceinline__ uint32_t tf_bits(uint32_t k0, uint32_t k1, uint32_t j)
{
    uint32_t o0, o1;
    tf2x32(k0, k1, 0u, j, o0, o1);
    return o0 ^ o1;
}

// ---------------- utility kernels -------------------------------------------
__global__ void k_zero()
{
    int i = blockIdx.x * blockDim.x + threadIdx.x;
    if (i < NN) { g_outdeg[i] = 0; g_indeg[i] = 0; g_fill[i] = 0; }
}

__global__ void k_deg(const int* __restrict__ src, const int* __restrict__ dst)
{
    int e = blockIdx.x * blockDim.x + threadIdx.x;
    if (e < EE) {
        atomicAdd(&g_outdeg[src[e]], 1);
        atomicAdd(&g_indeg [dst[e]], 1);
    }
}

// single-block exclusive scan of g_indeg -> g_off
__global__ void k_scan()
{
    __shared__ int warpsum[32];
    __shared__ int carry_sh;
    int tid = threadIdx.x, lane = tid & 31, wid = tid >> 5;
    if (tid == 0) carry_sh = 0;
    __syncthreads();
    for (int base = 0; base < NN; base += 1024) {
        int i = base + tid;
        int v = (i < NN) ? g_indeg[i] : 0;
        int incl = v;
#pragma unroll
        for (int o = 1; o < 32; o <<= 1) {
            int n = __shfl_up_sync(0xffffffffu, incl, o);
            if (lane >= o) incl += n;
        }
        if (lane == 31) warpsum[wid] = incl;
        __syncthreads();
        if (wid == 0) {
            int s = warpsum[lane];
#pragma unroll
            for (int o = 1; o < 32; o <<= 1) {
                int n = __shfl_up_sync(0xffffffffu, s, o);
                if (lane >= o) s += n;
            }
            warpsum[lane] = s;
        }
        __syncthreads();
        int wpre = (wid > 0) ? warpsum[wid - 1] : 0;
        int bc = carry_sh;
        if (i < NN) g_off[i] = bc + wpre + incl - v;
        __syncthreads();
        if (tid == 1023) carry_sh = bc + wpre + incl;
        __syncthreads();
    }
    if (threadIdx.x == 0) g_off[NN] = carry_sh;
}

__global__ void k_invsqrt()
{
    int i = blockIdx.x * blockDim.x + threadIdx.x;
    if (i < NN) {
        int od = g_outdeg[i]; if (od < 1) od = 1;
        int id = g_indeg [i]; if (id < 1) id = 1;
        g_out_is[i] = rsqrtf((float)od);
        g_in_is [i] = rsqrtf((float)id);
    }
}

__global__ void k_csrfill(const int* __restrict__ src, const int* __restrict__ dst)
{
    int e = blockIdx.x * blockDim.x + threadIdx.x;
    if (e < EE) {
        int d = dst[e];
        int p = atomicAdd(&g_fill[d], 1);
        g_csr[g_off[d] + p] = src[e];
    }
}

// ---------------- dropout(x)*2*out_is -> A1 (4 elems/thread) ----------------
__global__ void k_dropx(const float* __restrict__ x, uint32_t ka, uint32_t kb)
{
    int i = blockIdx.x * blockDim.x + threadIdx.x;    // grid exactly N*512/4
    int e = i * 4;
    int row = e >> 9;
    float s = 2.0f * g_out_is[row];
    float4 xv = *reinterpret_cast<const float4*>(&x[e]);
    float r[4];
    float xs[4] = { xv.x, xv.y, xv.z, xv.w };
#pragma unroll
    for (int q = 0; q < 4; q++) {
        uint32_t bits = tf_bits(ka, kb, (uint32_t)(e + q));
        r[q] = ((int)bits >= 0) ? xs[q] * s : 0.0f;
    }
    *reinterpret_cast<float4*>(&g_A1[e]) = make_float4(r[0], r[1], r[2], r[3]);
}

// ---------------- SGEMM1: t1 = A1[N,512] @ W1[512,256] ----------------------
__global__ __launch_bounds__(256) void k_gemm1(const float* __restrict__ W1)
{
    __shared__ float sA[16][68];
    __shared__ float sB[16][68];
    int tid = threadIdx.x;
    int bm = blockIdx.y * 64;
    int bn = blockIdx.x * 64;
    int tx = tid & 15, ty = tid >> 4;
    float acc[4][4] = {};
    for (int kt = 0; kt < 512; kt += 16) {
        {
            int r = tid >> 2;
            int k = (tid & 3) * 4;
            int gr = bm + r;
            float4 v = make_float4(0.f, 0.f, 0.f, 0.f);
            if (gr < NN)
                v = *reinterpret_cast<const float4*>(&g_A1[(size_t)gr * 512 + kt + k]);
            sA[k + 0][r] = v.x; sA[k + 1][r] = v.y;
            sA[k + 2][r] = v.z; sA[k + 3][r] = v.w;
        }
        {
            int k = tid >> 4;
            int c = (tid & 15) * 4;
            float4 v = *reinterpret_cast<const float4*>(&W1[(kt + k) * 256 + bn + c]);
            *reinterpret_cast<float4*>(&sB[k][c]) = v;
        }
        __syncthreads();
#pragma unroll
        for (int kk = 0; kk < 16; kk++) {
            float a[4], b[4];
            *(float4*)a = *(const float4*)&sA[kk][ty * 4];
            *(float4*)b = *(const float4*)&sB[kk][tx * 4];
#pragma unroll
            for (int i = 0; i < 4; i++)
#pragma unroll
                for (int j = 0; j < 4; j++)
                    acc[i][j] = fmaf(a[i], b[j], acc[i][j]);
        }
        __syncthreads();
    }
#pragma unroll
    for (int i = 0; i < 4; i++) {
        int gr = bm + ty * 4 + i;
        if (gr < NN)
            *reinterpret_cast<float4*>(&g_t1[(size_t)gr * 256 + bn + tx * 4]) = *(float4*)acc[i];
    }
}

// ---------------- agg1: h[d] = relu(in_is[d] * sum_src t1[src]) -------------
__global__ void k_agg1()
{
    int gw   = (blockIdx.x * blockDim.x + threadIdx.x) >> 5;
    int lane = threadIdx.x & 31;
    if (gw >= NN) return;
    int beg = g_off[gw], end = g_off[gw + 1];
    float4 a0 = make_float4(0.f, 0.f, 0.f, 0.f);
    float4 a1 = a0;
    const float4* base = reinterpret_cast<const float4*>(g_t1);
    for (int e = beg; e < end; e++) {
        int s = __ldg(&g_csr[e]);
        const float4* p = base + (size_t)s * 64 + lane * 2;
        float4 v0 = p[0];
        float4 v1 = p[1];
        a0.x += v0.x; a0.y += v0.y; a0.z += v0.z; a0.w += v0.w;
        a1.x += v1.x; a1.y += v1.y; a1.z += v1.z; a1.w += v1.w;
    }
    float sc = g_in_is[gw];
    float4 r0, r1;
    r0.x = fmaxf(a0.x * sc, 0.f); r0.y = fmaxf(a0.y * sc, 0.f);
    r0.z = fmaxf(a0.z * sc, 0.f); r0.w = fmaxf(a0.w * sc, 0.f);
    r1.x = fmaxf(a1.x * sc, 0.f); r1.y = fmaxf(a1.y * sc, 0.f);
    r1.z = fmaxf(a1.z * sc, 0.f); r1.w = fmaxf(a1.w * sc, 0.f);
    float4* outp = reinterpret_cast<float4*>(g_h) + (size_t)gw * 64 + lane * 2;
    outp[0] = r0;
    outp[1] = r1;
}

// ---------------- BatchNorm: deterministic two-stage stats ------------------
__global__ void k_bnstats()
{
    int c = threadIdx.x;
    float s = 0.f, ss = 0.f;
    for (int r = blockIdx.x; r < NN; r += 512) {
        float v = g_h[(size_t)r * 256 + c];
        s += v;
        ss = fmaf(v, v, ss);
    }
    g_part[blockIdx.x * 512 + c]       = s;
    g_part[blockIdx.x * 512 + 256 + c] = ss;
}

__global__ void k_bnreduce()
{
    int j = blockIdx.x * 256 + threadIdx.x;
    float s = 0.f;
    for (int b = 0; b < 512; b++) s += g_part[b * 512 + j];
    g_stats[j] = s;
}

__global__ void k_bnnorm()
{
    int i = blockIdx.x * blockDim.x + threadIdx.x;
    int c = i & 255;
    float m   = g_stats[c]       * (1.0f / NN);
    float var = g_stats[256 + c] * (1.0f / NN) - m * m;
    g_h[i] = (g_h[i] - m) * rsqrtf(var + 1e-5f);
}

// ---------------- masked A2/A3 (4 elems/thread, 8 threefry evals) -----------
__global__ void k_mask23(uint32_t a0k, uint32_t a1k, uint32_t b0k, uint32_t b1k)
{
    int i = blockIdx.x * blockDim.x + threadIdx.x;    // grid exactly N*256/4
    int e = i * 4;
    int row = e >> 8;
    float s = 2.0f * g_out_is[row];
    float4 hv = *reinterpret_cast<const float4*>(&g_h[e]);
    float hs[4] = { hv.x * s, hv.y * s, hv.z * s, hv.w * s };
    float r2[4], r3[4];
#pragma unroll
    for (int q = 0; q < 4; q++) {
        uint32_t pa = tf_bits(a0k, a1k, (uint32_t)(e + q));
        uint32_t pb = tf_bits(b0k, b1k, (uint32_t)(e + q));
        r2[q] = ((int)pa >= 0) ? hs[q] : 0.0f;
        r3[q] = ((int)pb >= 0) ? hs[q] : 0.0f;
    }
    *reinterpret_cast<float4*>(&g_A2[e]) = make_float4(r2[0], r2[1], r2[2], r2[3]);
    *reinterpret_cast<float4*>(&g_A3[e]) = make_float4(r3[0], r3[1], r3[2], r3[3]);
}

// ---------------- fused GEMM2/3: [N,256] x [256,16|16] -> mulv_pre ----------
__global__ __launch_bounds__(256) void k_gemm23(const float* __restrict__ W2,
                                                const float* __restrict__ W3)
{
    __shared__ float sA2[32][68];
    __shared__ float sA3[32][68];
    __shared__ float sB [32][36];
    int tid = threadIdx.x;
    int bm = blockIdx.x * 64;
    int c  = tid & 31;
    int rg = tid >> 5;
    float acc[8] = {};
    for (int kt = 0; kt < 256; kt += 32) {
        for (int i = tid; i < 2048; i += 256) {
            int r = i >> 5, k = i & 31;
            int gr = bm + r;
            float a2 = 0.f, a3 = 0.f;
            if (gr < NN) {
                size_t gi = (size_t)gr * 256 + kt + k;
                a2 = g_A2[gi];
                a3 = g_A3[gi];
            }
            sA2[k][r] = a2;
            sA3[k][r] = a3;
        }
        {
            int i = tid;
#pragma unroll
            for (int q = 0; q < 4; q++, i += 256) {
                int k = i >> 5, cc = i & 31;
                int gk = kt + k;
                sB[k][cc] = (cc < 16) ? W2[gk * 16 + cc] : W3[gk * 16 + cc - 16];
            }
        }
        __syncthreads();
        const float* sAx = (c < 16) ? &sA2[0][0] : &sA3[0][0];
#pragma unroll
        for (int kk = 0; kk < 32; kk++) {
            float b = sB[kk][c];
            const float4* pa = reinterpret_cast<const float4*>(sAx + kk * 68 + rg * 8);
            float4 v0 = pa[0], v1 = pa[1];
            acc[0] = fmaf(v0.x, b, acc[0]);
            acc[1] = fmaf(v0.y, b, acc[1]);
            acc[2] = fmaf(v0.z, b, acc[2]);
            acc[3] = fmaf(v0.w, b, acc[3]);
            acc[4] = fmaf(v1.x, b, acc[4]);
            acc[5] = fmaf(v1.y, b, acc[5]);
            acc[6] = fmaf(v1.z, b, acc[6]);
            acc[7] = fmaf(v1.w, b, acc[7]);
        }
        __syncthreads();
    }
#pragma unroll
    for (int i = 0; i < 8; i++) {
        int gr = bm + rg * 8 + i;
        if (gr < NN) g_mulv_pre[gr * 32 + c] = acc[i];
    }
}

// ---------------- agg2: 32-wide aggregation ---------------------------------
__global__ void k_agg2()
{
    int gw   = (blockIdx.x * blockDim.x + threadIdx.x) >> 5;
    int lane = threadIdx.x & 31;
    if (gw >= NN) return;
    int beg = g_off[gw], end = g_off[gw + 1];
    float acc = 0.f;
    for (int e = beg; e < end; e++) {
        int s = __ldg(&g_csr[e]);
        acc += g_mulv_pre[s * 32 + lane];
    }
    g_mulv[gw * 32 + lane] = acc * g_in_is[gw];
}

// ---------------- reparameterize (4 elems/thread) ----------------------------
__global__ void k_reparam(float* __restrict__ out, uint32_t k0, uint32_t k1)
{
    int i = blockIdx.x * blockDim.x + threadIdx.x;
    int e = i * 4;
    if (e >= NN * NCLS) return;
    int row = e >> 4;
    int c   = e & 15;
    const float* mrow = &g_mulv[row * 32];
    float4 mu = *reinterpret_cast<const float4*>(&mrow[c]);
    float4 lv = *reinterpret_cast<const float4*>(&mrow[16 + c]);
    float mus[4] = { mu.x, mu.y, mu.z, mu.w };
    float lvs[4] = { lv.x, lv.y, lv.z, lv.w };
    float r[4];
#pragma unroll
    for (int q = 0; q < 4; q++) {
        uint32_t bits = tf_bits(k0, k1, (uint32_t)(e + q));
        float f = __uint_as_float((bits >> 9) | 0x3f800000u) - 1.0f;
        float u = f * 2.0f - 0.99999994f;
        float eps = 1.4142135623730951f * erfinvf(u);
        r[q] = eps * expf(lvs[q]) + mus[q];
    }
    *reinterpret_cast<float4*>(&out[e]) = make_float4(r[0], r[1], r[2], r[3]);
}

// ---------------- launch -----------------------------------------------------
extern "C" void kernel_launch(void* const* d_in, const int* in_sizes, int n_in,
                              void* d_out, int out_size)
{
    const float* x    = (const float*)d_in[0];
    const float* W1   = (const float*)d_in[1];
    const float* W2   = (const float*)d_in[2];
    const float* W3   = (const float*)d_in[3];
    const int*   esrc = (const int*)d_in[4];
    const int*   edst = (const int*)d_in[5];
    float*       out  = (float*)d_out;

    // partitionable (fold-like) split of key(42) = (0, 42):
    // subkey i = threefry((0,42), (0, i)) -> (o0, o1)
    uint32_t k1a, k1b, k2a0, k2a1, k2b0, k2b1, ke0, ke1;
    tf2x32(0u, 42u, 0u, 0u, k1a,  k1b);   // k1
    tf2x32(0u, 42u, 0u, 1u, k2a0, k2a1);  // k2a
    tf2x32(0u, 42u, 0u, 2u, k2b0, k2b1);  // k2b
    tf2x32(0u, 42u, 0u, 3u, ke0,  ke1);   // keps

    k_zero   <<<(NN + 255) / 256, 256>>>();
    k_deg    <<<EE / 256, 256>>>(esrc, edst);
    k_scan   <<<1, 1024>>>();
    k_invsqrt<<<(NN + 255) / 256, 256>>>();
    k_csrfill<<<EE / 256, 256>>>(esrc, edst);

    k_dropx  <<<(NN * INDIM / 4) / 256, 256>>>(x, k1a, k1b);

    dim3 g1(HIDD / 64, (NN + 63) / 64);
    k_gemm1  <<<g1, 256>>>(W1);

    k_agg1   <<<(NN * 32 + 255) / 256, 256>>>();

    k_bnstats <<<512, 256>>>();
    k_bnreduce<<<2, 256>>>();
    k_bnnorm  <<<(NN * HIDD) / 256, 256>>>();

    k_mask23 <<<(NN * HIDD / 4) / 256, 256>>>(k2a0, k2a1, k2b0, k2b1);
    k_gemm23 <<<(NN + 63) / 64, 256>>>(W2, W3);
    k_agg2   <<<(NN * 32 + 255) / 256, 256>>>();

    k_reparam<<<(NN * NCLS / 4 + 255) / 256, 256>>>(out, ke0, ke1);
}

// round 4
// speedup vs baseline: 1.0439x; 1.0439x over previous
#include <cuda_runtime.h>
#include <stdint.h>

#define NN      100000
#define EE      3200000
#define INDIM   512
#define HIDD    256
#define NCLS    16

// ---------------- static device scratch ------------------------------------
__device__ float    g_t1[(size_t)NN * HIDD];
__device__ float    g_h [(size_t)NN * HIDD];
__device__ float    g_mulv_pre[NN * 32];
__device__ float    g_mulv    [NN * 32];
__device__ uint32_t g_mask1[(size_t)NN * INDIM / 32];
__device__ uint32_t g_mask2[(size_t)NN * HIDD / 32];
__device__ uint32_t g_mask3[(size_t)NN * HIDD / 32];
__device__ int      g_outdeg[NN];
__device__ int      g_indeg [NN];
__device__ int      g_fill  [NN];
__device__ int      g_off   [NN + 1];
__device__ int      g_csr   [EE];
__device__ float    g_out_is[NN];
__device__ float    g_in_is [NN];
__device__ float    g_part  [512 * 512];
__device__ float    g_stats [512];

// ---------------- threefry2x32 (JAX-exact core) -----------------------------
__host__ __device__ __forceinline__ void tf2x32(uint32_t k0, uint32_t k1,
                                                uint32_t x0, uint32_t x1,
                                                uint32_t &o0, uint32_t &o1)
{
    uint32_t ks2 = k0 ^ k1 ^ 0x1BD11BDAu;
#define TF_ROT(v, r) (((v) << (r)) | ((v) >> (32 - (r))))
#define TF_RND(r) { x0 += x1; x1 = TF_ROT(x1, r); x1 ^= x0; }
    x0 += k0; x1 += k1;
    TF_RND(13) TF_RND(15) TF_RND(26) TF_RND(6)
    x0 += k1;  x1 += ks2 + 1u;
    TF_RND(17) TF_RND(29) TF_RND(16) TF_RND(24)
    x0 += ks2; x1 += k0 + 2u;
    TF_RND(13) TF_RND(15) TF_RND(26) TF_RND(6)
    x0 += k0;  x1 += k1 + 3u;
    TF_RND(17) TF_RND(29) TF_RND(16) TF_RND(24)
    x0 += k1;  x1 += ks2 + 4u;
    TF_RND(13) TF_RND(15) TF_RND(26) TF_RND(6)
    x0 += ks2; x1 += k0 + 5u;
    o0 = x0; o1 = x1;
#undef TF_RND
#undef TF_ROT
}

__device__ __forceinline__ uint32_t tf_bits(uint32_t k0, uint32_t k1, uint32_t j)
{
    uint32_t o0, o1;
    tf2x32(k0, k1, 0u, j, o0, o1);
    return o0 ^ o1;
}

// ---------------- graph setup -------------------------------------------------
__global__ void k_zero()
{
    int i = blockIdx.x * blockDim.x + threadIdx.x;
    if (i < NN) { g_outdeg[i] = 0; g_indeg[i] = 0; g_fill[i] = 0; }
}

__global__ void k_deg(const int* __restrict__ src, const int* __restrict__ dst)
{
    int e = blockIdx.x * blockDim.x + threadIdx.x;
    if (e < EE) {
        atomicAdd(&g_outdeg[src[e]], 1);
        atomicAdd(&g_indeg [dst[e]], 1);
    }
}

__global__ void k_scan()
{
    __shared__ int warpsum[32];
    __shared__ int carry_sh;
    int tid = threadIdx.x, lane = tid & 31, wid = tid >> 5;
    if (tid == 0) carry_sh = 0;
    __syncthreads();
    for (int base = 0; base < NN; base += 1024) {
        int i = base + tid;
        int v = (i < NN) ? g_indeg[i] : 0;
        int incl = v;
#pragma unroll
        for (int o = 1; o < 32; o <<= 1) {
            int n = __shfl_up_sync(0xffffffffu, incl, o);
            if (lane >= o) incl += n;
        }
        if (lane == 31) warpsum[wid] = incl;
        __syncthreads();
        if (wid == 0) {
            int s = warpsum[lane];
#pragma unroll
            for (int o = 1; o < 32; o <<= 1) {
                int n = __shfl_up_sync(0xffffffffu, s, o);
                if (lane >= o) s += n;
            }
            warpsum[lane] = s;
        }
        __syncthreads();
        int wpre = (wid > 0) ? warpsum[wid - 1] : 0;
        int bc = carry_sh;
        if (i < NN) g_off[i] = bc + wpre + incl - v;
        __syncthreads();
        if (tid == 1023) carry_sh = bc + wpre + incl;
        __syncthreads();
    }
    if (threadIdx.x == 0) g_off[NN] = carry_sh;
}

__global__ void k_invsqrt()
{
    int i = blockIdx.x * blockDim.x + threadIdx.x;
    if (i < NN) {
        int od = g_outdeg[i]; if (od < 1) od = 1;
        int id = g_indeg [i]; if (id < 1) id = 1;
        g_out_is[i] = rsqrtf((float)od);
        g_in_is [i] = rsqrtf((float)id);
    }
}

__global__ void k_csrfill(const int* __restrict__ src, const int* __restrict__ dst)
{
    int e = blockIdx.x * blockDim.x + threadIdx.x;
    if (e < EE) {
        int d = dst[e];
        int p = atomicAdd(&g_fill[d], 1);
        g_csr[g_off[d] + p] = src[e];
    }
}

// ---------------- dropout bitmask generation --------------------------------
__global__ void k_mask1(uint32_t ka, uint32_t kb)
{
    int e = blockIdx.x * blockDim.x + threadIdx.x;   // grid exactly N*512
    uint32_t bits = tf_bits(ka, kb, (uint32_t)e);
    uint32_t w = __ballot_sync(0xffffffffu, (int)bits >= 0);
    if ((e & 31) == 0) g_mask1[e >> 5] = w;
}

__global__ void k_mask2(uint32_t a0, uint32_t a1, uint32_t b0, uint32_t b1)
{
    int e = blockIdx.x * blockDim.x + threadIdx.x;   // grid exactly N*256
    uint32_t pa = tf_bits(a0, a1, (uint32_t)e);
    uint32_t pb = tf_bits(b0, b1, (uint32_t)e);
    uint32_t w2 = __ballot_sync(0xffffffffu, (int)pa >= 0);
    uint32_t w3 = __ballot_sync(0xffffffffu, (int)pb >= 0);
    if ((e & 31) == 0) {
        g_mask2[e >> 5] = w2;
        g_mask3[e >> 5] = w3;
    }
}

// ---------------- GEMM1: t1 = (mask1 . x * 2*out_is) @ W1 -------------------
// 128x128x16 tiles, double-buffered, 8x8 microtile, 256 threads
__global__ __launch_bounds__(256) void k_gemm1(const float* __restrict__ x,
                                               const float* __restrict__ W1)
{
    __shared__ float sA[2][16][132];
    __shared__ float sB[2][16][132];
    int tid = threadIdx.x;
    int bm = blockIdx.y * 128;
    int bn = blockIdx.x * 128;
    int tx = tid & 15, ty = tid >> 4;

    // A loader: f4 = tid + 256*j ; r = f4>>2 ; k4 = (f4&3)*4
    int ar = tid >> 2;
    int ak = (tid & 3) * 4;
    int gr0 = bm + ar;
    int gr1 = gr0 + 64;
    float s0 = 2.0f * g_out_is[gr0 < NN ? gr0 : NN - 1];
    float s1 = 2.0f * g_out_is[gr1 < NN ? gr1 : NN - 1];
    // B loader: k = tid>>4 ; c = (tid&15)*8
    int bk = tid >> 4;
    int bc = (tid & 15) * 8;

#define LOAD_TILES(KT, BUF)                                                    \
    {                                                                          \
        int kt_ = (KT);                                                        \
        _Pragma("unroll")                                                      \
        for (int j = 0; j < 2; j++) {                                          \
            int r = ar + j * 64;                                               \
            int gr = bm + r;                                                   \
            float4 v = make_float4(0.f, 0.f, 0.f, 0.f);                        \
            uint32_t mw = 0;                                                   \
            if (gr < NN) {                                                     \
                size_t idx = (size_t)gr * 512 + kt_ + ak;                      \
                v = *reinterpret_cast<const float4*>(&x[idx]);                 \
                mw = g_mask1[idx >> 5];                                        \
            }                                                                  \
            float s = j ? s1 : s0;                                             \
            int sh = (kt_ & 16) + ak;                                          \
            sA[BUF][ak + 0][r] = ((mw >> (sh + 0)) & 1u) ? v.x * s : 0.f;      \
            sA[BUF][ak + 1][r] = ((mw >> (sh + 1)) & 1u) ? v.y * s : 0.f;      \
            sA[BUF][ak + 2][r] = ((mw >> (sh + 2)) & 1u) ? v.z * s : 0.f;      \
            sA[BUF][ak + 3][r] = ((mw >> (sh + 3)) & 1u) ? v.w * s : 0.f;      \
        }                                                                      \
        const float* wp = &W1[(size_t)(kt_ + bk) * 256 + bn + bc];             \
        float4 w0 = *reinterpret_cast<const float4*>(wp);                      \
        float4 w1 = *reinterpret_cast<const float4*>(wp + 4);                  \
        *reinterpret_cast<float4*>(&sB[BUF][bk][bc])     = w0;                 \
        *reinterpret_cast<float4*>(&sB[BUF][bk][bc + 4]) = w1;                 \
    }

    float acc[8][8] = {};
    LOAD_TILES(0, 0)
    __syncthreads();
    int buf = 0;
    for (int kt = 0; kt < 512; kt += 16) {
        if (kt + 16 < 512) LOAD_TILES(kt + 16, buf ^ 1)
#pragma unroll
        for (int kk = 0; kk < 16; kk++) {
            float a[8], b[8];
            *(float4*)&a[0] = *(const float4*)&sA[buf][kk][ty * 8];
            *(float4*)&a[4] = *(const float4*)&sA[buf][kk][ty * 8 + 4];
            *(float4*)&b[0] = *(const float4*)&sB[buf][kk][tx * 8];
            *(float4*)&b[4] = *(const float4*)&sB[buf][kk][tx * 8 + 4];
#pragma unroll
            for (int i = 0; i < 8; i++)
#pragma unroll
                for (int j = 0; j < 8; j++)
                    acc[i][j] = fmaf(a[i], b[j], acc[i][j]);
        }
        __syncthreads();
        buf ^= 1;
    }
#pragma unroll
    for (int i = 0; i < 8; i++) {
        int gr = bm + ty * 8 + i;
        if (gr < NN) {
            float* op = &g_t1[(size_t)gr * 256 + bn + tx * 8];
            *reinterpret_cast<float4*>(op)     = *(float4*)&acc[i][0];
            *reinterpret_cast<float4*>(op + 4) = *(float4*)&acc[i][4];
        }
    }
#undef LOAD_TILES
}

// ---------------- agg1 (two 128-col passes for L2 residency) ----------------
template<int CB>
__global__ void k_agg1()
{
    int gw   = (blockIdx.x * blockDim.x + threadIdx.x) >> 5;
    int lane = threadIdx.x & 31;
    if (gw >= NN) return;
    int beg = g_off[gw], end = g_off[gw + 1];
    float ax = 0.f, ay = 0.f, az = 0.f, aw = 0.f;
    const float* base = g_t1 + CB + lane * 4;
    int e = beg;
    for (; e + 1 < end; e += 2) {
        int s0 = __ldg(&g_csr[e]);
        int s1 = __ldg(&g_csr[e + 1]);
        float4 v0 = *reinterpret_cast<const float4*>(base + (size_t)s0 * 256);
        float4 v1 = *reinterpret_cast<const float4*>(base + (size_t)s1 * 256);
        ax += v0.x; ay += v0.y; az += v0.z; aw += v0.w;
        ax += v1.x; ay += v1.y; az += v1.z; aw += v1.w;
    }
    if (e < end) {
        int s0 = __ldg(&g_csr[e]);
        float4 v0 = *reinterpret_cast<const float4*>(base + (size_t)s0 * 256);
        ax += v0.x; ay += v0.y; az += v0.z; aw += v0.w;
    }
    float sc = g_in_is[gw];
    float4 r;
    r.x = fmaxf(ax * sc, 0.f); r.y = fmaxf(ay * sc, 0.f);
    r.z = fmaxf(az * sc, 0.f); r.w = fmaxf(aw * sc, 0.f);
    *reinterpret_cast<float4*>(&g_h[(size_t)gw * 256 + CB + lane * 4]) = r;
}

// ---------------- BN stats (deterministic) ----------------------------------
__global__ void k_bnstats()
{
    int c = threadIdx.x;
    float s = 0.f, ss = 0.f;
    for (int r = blockIdx.x; r < NN; r += 512) {
        float v = g_h[(size_t)r * 256 + c];
        s += v;
        ss = fmaf(v, v, ss);
    }
    g_part[blockIdx.x * 512 + c]       = s;
    g_part[blockIdx.x * 512 + 256 + c] = ss;
}

__global__ void k_bnreduce()
{
    int j = blockIdx.x * 256 + threadIdx.x;
    float s = 0.f;
    for (int b = 0; b < 512; b++) s += g_part[b * 512 + j];
    g_stats[j] = s;   // raw sums; mean/istd derived in gemm23
}

// ---------------- GEMM2/3 fused with BN + dropout masks ---------------------
__global__ __launch_bounds__(256) void k_gemm23(const float* __restrict__ W2,
                                                const float* __restrict__ W3)
{
    __shared__ float sA2[32][68];
    __shared__ float sA3[32][68];
    __shared__ float sB [32][36];
    __shared__ float sMean[256], sIstd[256], sScale[64];
    int tid = threadIdx.x;
    int bm = blockIdx.x * 64;
    int c  = tid & 31;
    int rg = tid >> 5;

    {
        float sum  = g_stats[tid];
        float sums = g_stats[256 + tid];
        float m    = sum * (1.0f / NN);
        float var  = sums * (1.0f / NN) - m * m;
        sMean[tid] = m;
        sIstd[tid] = rsqrtf(var + 1e-5f);
        if (tid < 64) {
            int gr = bm + tid;
            sScale[tid] = 2.0f * g_out_is[gr < NN ? gr : NN - 1];
        }
    }
    __syncthreads();

    float acc[8] = {};
    for (int kt = 0; kt < 256; kt += 32) {
        for (int i = tid; i < 2048; i += 256) {
            int r = i >> 5, k = i & 31;
            int gr = bm + r;
            float a2 = 0.f, a3 = 0.f;
            if (gr < NN) {
                size_t gi = (size_t)gr * 256 + kt + k;
                float hv = g_h[gi];
                float hbn = (hv - sMean[kt + k]) * sIstd[kt + k] * sScale[r];
                uint32_t w2 = g_mask2[gi >> 5];
                uint32_t w3 = g_mask3[gi >> 5];
                a2 = ((w2 >> (k & 31)) & 1u) ? hbn : 0.f;
                a3 = ((w3 >> (k & 31)) & 1u) ? hbn : 0.f;
            }
            sA2[k][r] = a2;
            sA3[k][r] = a3;
        }
        {
            int i = tid;
#pragma unroll
            for (int q = 0; q < 4; q++, i += 256) {
                int k = i >> 5, cc = i & 31;
                int gk = kt + k;
                sB[k][cc] = (cc < 16) ? W2[gk * 16 + cc] : W3[gk * 16 + cc - 16];
            }
        }
        __syncthreads();
        const float* sAx = (c < 16) ? &sA2[0][0] : &sA3[0][0];
#pragma unroll
        for (int kk = 0; kk < 32; kk++) {
            float b = sB[kk][c];
            const float4* pa = reinterpret_cast<const float4*>(sAx + kk * 68 + rg * 8);
            float4 v0 = pa[0], v1 = pa[1];
            acc[0] = fmaf(v0.x, b, acc[0]);
            acc[1] = fmaf(v0.y, b, acc[1]);
            acc[2] = fmaf(v0.z, b, acc[2]);
            acc[3] = fmaf(v0.w, b, acc[3]);
            acc[4] = fmaf(v1.x, b, acc[4]);
            acc[5] = fmaf(v1.y, b, acc[5]);
            acc[6] = fmaf(v1.z, b, acc[6]);
            acc[7] = fmaf(v1.w, b, acc[7]);
        }
        __syncthreads();
    }
#pragma unroll
    for (int i = 0; i < 8; i++) {
        int gr = bm + rg * 8 + i;
        if (gr < NN) g_mulv_pre[gr * 32 + c] = acc[i];
    }
}

// ---------------- agg2 --------------------------------------------------------
__global__ void k_agg2()
{
    int gw   = (blockIdx.x * blockDim.x + threadIdx.x) >> 5;
    int lane = threadIdx.x & 31;
    if (gw >= NN) return;
    int beg = g_off[gw], end = g_off[gw + 1];
    float acc = 0.f;
    int e = beg;
    for (; e + 1 < end; e += 2) {
        int s0 = __ldg(&g_csr[e]);
        int s1 = __ldg(&g_csr[e + 1]);
        acc += g_mulv_pre[s0 * 32 + lane];
        acc += g_mulv_pre[s1 * 32 + lane];
    }
    if (e < end) {
        int s0 = __ldg(&g_csr[e]);
        acc += g_mulv_pre[s0 * 32 + lane];
    }
    g_mulv[gw * 32 + lane] = acc * g_in_is[gw];
}

// ---------------- reparameterize ----------------------------------------------
__global__ void k_reparam(float* __restrict__ out, uint32_t k0, uint32_t k1)
{
    int i = blockIdx.x * blockDim.x + threadIdx.x;
    int e = i * 4;
    if (e >= NN * NCLS) return;
    int row = e >> 4;
    int c   = e & 15;
    const float* mrow = &g_mulv[row * 32];
    float4 mu = *reinterpret_cast<const float4*>(&mrow[c]);
    float4 lv = *reinterpret_cast<const float4*>(&mrow[16 + c]);
    float mus[4] = { mu.x, mu.y, mu.z, mu.w };
    float lvs[4] = { lv.x, lv.y, lv.z, lv.w };
    float r[4];
#pragma unroll
    for (int q = 0; q < 4; q++) {
        uint32_t bits = tf_bits(k0, k1, (uint32_t)(e + q));
        float f = __uint_as_float((bits >> 9) | 0x3f800000u) - 1.0f;
        float u = f * 2.0f - 0.99999994f;
        float eps = 1.4142135623730951f * erfinvf(u);
        r[q] = eps * expf(lvs[q]) + mus[q];
    }
    *reinterpret_cast<float4*>(&out[e]) = make_float4(r[0], r[1], r[2], r[3]);
}

// ---------------- launch --------------------------------------------------------
extern "C" void kernel_launch(void* const* d_in, const int* in_sizes, int n_in,
                              void* d_out, int out_size)
{
    const float* x    = (const float*)d_in[0];
    const float* W1   = (const float*)d_in[1];
    const float* W2   = (const float*)d_in[2];
    const float* W3   = (const float*)d_in[3];
    const int*   esrc = (const int*)d_in[4];
    const int*   edst = (const int*)d_in[5];
    float*       out  = (float*)d_out;

    // partitionable split of key(42) = (0, 42): subkey i = tf((0,42),(0,i))
    uint32_t k1a, k1b, k2a0, k2a1, k2b0, k2b1, ke0, ke1;
    tf2x32(0u, 42u, 0u, 0u, k1a,  k1b);
    tf2x32(0u, 42u, 0u, 1u, k2a0, k2a1);
    tf2x32(0u, 42u, 0u, 2u, k2b0, k2b1);
    tf2x32(0u, 42u, 0u, 3u, ke0,  ke1);

    k_zero   <<<(NN + 255) / 256, 256>>>();
    k_deg    <<<EE / 256, 256>>>(esrc, edst);
    k_scan   <<<1, 1024>>>();
    k_invsqrt<<<(NN + 255) / 256, 256>>>();
    k_csrfill<<<EE / 256, 256>>>(esrc, edst);

    k_mask1  <<<NN * INDIM / 256, 256>>>(k1a, k1b);
    k_mask2  <<<NN * HIDD  / 256, 256>>>(k2a0, k2a1, k2b0, k2b1);

    dim3 g1(2, (NN + 127) / 128);
    k_gemm1  <<<g1, 256>>>(x, W1);

    k_agg1<0>   <<<(NN * 32) / 256, 256>>>();
    k_agg1<128> <<<(NN * 32) / 256, 256>>>();

    k_bnstats <<<512, 256>>>();
    k_bnreduce<<<2, 256>>>();

    k_gemm23 <<<(NN + 63) / 64, 256>>>(W2, W3);
    k_agg2   <<<(NN * 32) / 256, 256>>>();

    k_reparam<<<(NN * NCLS / 4 + 255) / 256, 256>>>(out, ke0, ke1);
}